// round 6
// baseline (speedup 1.0000x reference)
#include <cuda_runtime.h>
#include <math.h>

#define B_TOTAL 16384
#define T_LEN   512
#define NSTEP   511
#define HDIM    32
#define WID     64
#define BLK     128
#define NGROUPS 256          /* 16384 / 64 elements per CTA */
#define GRID    256

typedef unsigned long long u64;

// Tsit5 coefficients
__constant__ float cA[6][5] = {
    {0.f, 0.f, 0.f, 0.f, 0.f},
    {0.161f, 0.f, 0.f, 0.f, 0.f},
    {-0.008480655492356989f, 0.335480655492357f, 0.f, 0.f, 0.f},
    {2.8971530571054935f, -6.359448489975075f, 4.3622954328695815f, 0.f, 0.f},
    {5.325864828439257f, -11.748883564062828f, 7.4955393428898365f, -0.09249506636175525f, 0.f},
    {5.86145544294642f, -12.92096931784711f, 8.159367898576159f, -0.071584973281401f, -0.028269050394068383f}
};
__constant__ float cB[6] = {
    0.09646076681806523f, 0.01f, 0.4798896504144996f,
    1.379008574103742f, -3.290069515436081f, 2.324710524099774f
};

// ---- packed f32x2 helpers ----
__device__ __forceinline__ u64 pack2(float lo, float hi) {
    u64 r; asm("mov.b64 %0, {%1, %2};" : "=l"(r) : "f"(lo), "f"(hi)); return r;
}
__device__ __forceinline__ void unpack2(u64 v, float& lo, float& hi) {
    asm("mov.b64 {%0, %1}, %2;" : "=f"(lo), "=f"(hi) : "l"(v));
}
__device__ __forceinline__ u64 dup2(float x) { return pack2(x, x); }
__device__ __forceinline__ u64 fma2(u64 a, u64 b, u64 c) {
    u64 d; asm("fma.rn.f32x2 %0, %1, %2, %3;" : "=l"(d) : "l"(a), "l"(b), "l"(c)); return d;
}

// SMEM layout (floats)
#define OFF_W1T 0                      /* [i=32][j=64] transposed : 2048 */
#define OFF_W2T (OFF_W1T + 2048)       /* [i=64][j=64]            : 4096 */
#define OFF_W3T (OFF_W2T + 4096)       /* [i=64][r=96]            : 6144 */
#define OFF_B1  (OFF_W3T + 6144)       /* 64 */
#define OFF_B2  (OFF_B1 + 64)          /* 64 */
#define OFF_B3  (OFF_B2 + 64)          /* 96 */
#define OFF_Y   (OFF_B3 + 96)          /* u64 [32 comp][32 lane] : 2048 floats */
#define OFF_H1  (OFF_Y + 2048)         /* u64 [64][32] : 4096 floats */
#define OFF_H2  (OFF_H1 + 4096)        /* u64 [64][32] : 4096 floats */
#define SMEM_FLOATS (OFF_H2 + 4096)
#define SMEM_BYTES  (SMEM_FLOATS * 4)  /* 91,008 B -> 2 CTAs/SM */

__device__ __forceinline__ float tanh_fast(float x) {
    float xc = fminf(fmaxf(x, -15.0f), 15.0f);
    float e  = __expf(2.0f * xc);
    return __fdividef(e - 1.0f, e + 1.0f);
}

__global__ void __launch_bounds__(BLK, 2)
neural_cde_kernel(const float* __restrict__ times,
                  const float* __restrict__ grads,
                  const float* __restrict__ w1g,
                  const float* __restrict__ b1g,
                  const float* __restrict__ w2g,
                  const float* __restrict__ b2g,
                  const float* __restrict__ w3g,
                  const float* __restrict__ b3g,
                  const float* __restrict__ wencg,
                  const float* __restrict__ bencg,
                  const float* __restrict__ wrog,
                  const float* __restrict__ brog,
                  float* __restrict__ out)
{
    extern __shared__ float sm[];
    float* w1t  = sm + OFF_W1T;
    float* w2t  = sm + OFF_W2T;
    float* w3t  = sm + OFF_W3T;
    float* b1s  = sm + OFF_B1;
    float* b2s  = sm + OFF_B2;
    float* b3s  = sm + OFF_B3;
    u64*   ysm  = (u64*)(sm + OFF_Y);
    u64*   h1sm = (u64*)(sm + OFF_H1);
    u64*   h2sm = (u64*)(sm + OFF_H2);

    const int tid  = threadIdx.x;
    const int w    = tid >> 5;
    const int lane = tid & 31;

    // ---- stage weights (transposed) ----
    for (int idx = tid; idx < 2048; idx += BLK) {        // w1: [64][32] -> w1t[i][j]
        int j = idx >> 5, i = idx & 31;
        w1t[i * 64 + j] = w1g[idx];
    }
    for (int idx = tid; idx < 4096; idx += BLK) {        // w2: [64][64] -> w2t[i][j]
        int j = idx >> 6, i = idx & 63;
        w2t[i * 64 + j] = w2g[idx];
    }
    for (int idx = tid; idx < 6144; idx += BLK) {        // w3: [96][64] -> w3t[i][r]
        int r = idx >> 6, i = idx & 63;
        w3t[i * 96 + r] = w3g[idx];
    }
    for (int idx = tid; idx < 64; idx += BLK) b1s[idx] = b1g[idx];
    for (int idx = tid; idx < 64; idx += BLK) b2s[idx] = b2g[idx];
    for (int idx = tid; idx < 96; idx += BLK) b3s[idx] = b3g[idx];
    __syncthreads();

    const float dt = times[1] - times[0];

    const int g  = blockIdx.x;
    const int eA = g * 64 + lane;
    const int eB = eA + 32;
    const float* gA = grads + (size_t)eA * T_LEN * 3;
    const float* gB = grads + (size_t)eB * T_LEN * 3;

    // packed per-thread state: comps [8w,8w+8), halves = (elemA, elemB)
    u64 zp[8], k0p[8], k1p[8], k2p[8], k3p[8], k4p[8], kvp[8];
#pragma unroll
    for (int p = 0; p < 8; p++) {
        int c = 8 * w + p;
        zp[p] = dup2(wencg[c] + bencg[c]);
        k0p[p] = k1p[p] = k2p[p] = k3p[p] = k4p[p] = 0ull;
    }

    const u64 bw0 = dup2(cB[0]), bw1 = dup2(cB[1]), bw2 = dup2(cB[2]);
    const u64 bw3 = dup2(cB[3]), bw4 = dup2(cB[4]), bw5 = dup2(cB[5]);

#pragma unroll 1
    for (int n = 0; n < NSTEP; n++) {
        const float dqA0 = gA[n * 3 + 0] * dt;
        const float dqA1 = gA[n * 3 + 1] * dt;
        const float dqA2 = gA[n * 3 + 2] * dt;
        const float dqB0 = gB[n * 3 + 0] * dt;
        const float dqB1 = gB[n * 3 + 1] * dt;
        const float dqB2 = gB[n * 3 + 2] * dt;

#pragma unroll 1
        for (int s = 0; s < 6; s++) {
            const u64 a0 = dup2(cA[s][0]), a1 = dup2(cA[s][1]);
            const u64 a2 = dup2(cA[s][2]), a3 = dup2(cA[s][3]);
            const u64 a4 = dup2(cA[s][4]);

            // phase 1: y slice -> smem (zero coeffs are exact no-ops)
#pragma unroll
            for (int p = 0; p < 8; p++) {
                u64 acc = zp[p];
                acc = fma2(a0, k0p[p], acc);
                acc = fma2(a1, k1p[p], acc);
                acc = fma2(a2, k2p[p], acc);
                acc = fma2(a3, k3p[p], acc);
                acc = fma2(a4, k4p[p], acc);
                ysm[(8 * w + p) * 32 + lane] = acc;
            }
            __syncthreads();

            // phase 2: L1 rows [16w,16w+16); acc pairs over (r, r+1)
            {
                u64 accA[8], accB[8];
                const u64* bp = (const u64*)(b1s + 16 * w);
#pragma unroll
                for (int u = 0; u < 8; u++) { accA[u] = bp[u]; accB[u] = bp[u]; }
#pragma unroll 8
                for (int i = 0; i < HDIM; i++) {
                    float yA, yB;
                    unpack2(ysm[i * 32 + lane], yA, yB);
                    const u64 dA = dup2(yA), dB = dup2(yB);
                    const ulonglong2* wp = (const ulonglong2*)(w1t + i * 64 + 16 * w);
#pragma unroll
                    for (int q = 0; q < 4; q++) {
                        ulonglong2 wq = wp[q];
                        accA[2 * q + 0] = fma2(wq.x, dA, accA[2 * q + 0]);
                        accA[2 * q + 1] = fma2(wq.y, dA, accA[2 * q + 1]);
                        accB[2 * q + 0] = fma2(wq.x, dB, accB[2 * q + 0]);
                        accB[2 * q + 1] = fma2(wq.y, dB, accB[2 * q + 1]);
                    }
                }
#pragma unroll
                for (int u = 0; u < 8; u++) {
                    float aA0, aA1, aB0, aB1;
                    unpack2(accA[u], aA0, aA1);
                    unpack2(accB[u], aB0, aB1);
                    int r0 = 16 * w + 2 * u;
                    h1sm[r0 * 32 + lane]       = pack2(tanh_fast(aA0), tanh_fast(aB0));
                    h1sm[(r0 + 1) * 32 + lane] = pack2(tanh_fast(aA1), tanh_fast(aB1));
                }
            }
            __syncthreads();

            // phase 3: L2 rows [16w,16w+16)
            {
                u64 accA[8], accB[8];
                const u64* bp = (const u64*)(b2s + 16 * w);
#pragma unroll
                for (int u = 0; u < 8; u++) { accA[u] = bp[u]; accB[u] = bp[u]; }
#pragma unroll 8
                for (int i = 0; i < WID; i++) {
                    float hA, hB;
                    unpack2(h1sm[i * 32 + lane], hA, hB);
                    const u64 dA = dup2(hA), dB = dup2(hB);
                    const ulonglong2* wp = (const ulonglong2*)(w2t + i * 64 + 16 * w);
#pragma unroll
                    for (int q = 0; q < 4; q++) {
                        ulonglong2 wq = wp[q];
                        accA[2 * q + 0] = fma2(wq.x, dA, accA[2 * q + 0]);
                        accA[2 * q + 1] = fma2(wq.y, dA, accA[2 * q + 1]);
                        accB[2 * q + 0] = fma2(wq.x, dB, accB[2 * q + 0]);
                        accB[2 * q + 1] = fma2(wq.y, dB, accB[2 * q + 1]);
                    }
                }
#pragma unroll
                for (int u = 0; u < 8; u++) {
                    float aA0, aA1, aB0, aB1;
                    unpack2(accA[u], aA0, aA1);
                    unpack2(accB[u], aB0, aB1);
                    int r0 = 16 * w + 2 * u;
                    h2sm[r0 * 32 + lane]       = pack2(tanh_fast(aA0), tanh_fast(aB0));
                    h2sm[(r0 + 1) * 32 + lane] = pack2(tanh_fast(aA1), tanh_fast(aB1));
                }
            }
            __syncthreads();

            // phase 4: L3 rows [24w,24w+24) + dq contraction
            {
                u64 accA[12], accB[12];
                const u64* bp = (const u64*)(b3s + 24 * w);
#pragma unroll
                for (int u = 0; u < 12; u++) { accA[u] = bp[u]; accB[u] = bp[u]; }
#pragma unroll 8
                for (int i = 0; i < WID; i++) {
                    float hA, hB;
                    unpack2(h2sm[i * 32 + lane], hA, hB);
                    const u64 dA = dup2(hA), dB = dup2(hB);
                    const ulonglong2* wp = (const ulonglong2*)(w3t + i * 96 + 24 * w);
#pragma unroll
                    for (int q = 0; q < 6; q++) {
                        ulonglong2 wq = wp[q];
                        accA[2 * q + 0] = fma2(wq.x, dA, accA[2 * q + 0]);
                        accA[2 * q + 1] = fma2(wq.y, dA, accA[2 * q + 1]);
                        accB[2 * q + 0] = fma2(wq.x, dB, accB[2 * q + 0]);
                        accB[2 * q + 1] = fma2(wq.y, dB, accB[2 * q + 1]);
                    }
                }
                float fA[24], fB[24];
#pragma unroll
                for (int u = 0; u < 12; u++) {
                    unpack2(accA[u], fA[2 * u], fA[2 * u + 1]);
                    unpack2(accB[u], fB[2 * u], fB[2 * u + 1]);
                }
#pragma unroll
                for (int p = 0; p < 8; p++) {
                    float kA = fA[3 * p] * dqA0;
                    kA = fmaf(fA[3 * p + 1], dqA1, kA);
                    kA = fmaf(fA[3 * p + 2], dqA2, kA);
                    float kB = fB[3 * p] * dqB0;
                    kB = fmaf(fB[3 * p + 1], dqB1, kB);
                    kB = fmaf(fB[3 * p + 2], dqB2, kB);
                    kvp[p] = pack2(kA, kB);
                }
            }

            if (s == 0) {
#pragma unroll
                for (int p = 0; p < 8; p++) k0p[p] = kvp[p];
            } else if (s == 1) {
#pragma unroll
                for (int p = 0; p < 8; p++) k1p[p] = kvp[p];
            } else if (s == 2) {
#pragma unroll
                for (int p = 0; p < 8; p++) k2p[p] = kvp[p];
            } else if (s == 3) {
#pragma unroll
                for (int p = 0; p < 8; p++) k3p[p] = kvp[p];
            } else if (s == 4) {
#pragma unroll
                for (int p = 0; p < 8; p++) k4p[p] = kvp[p];
            }
        } // stages

#pragma unroll
        for (int p = 0; p < 8; p++) {
            u64 acc = fma2(bw5, kvp[p], zp[p]);
            acc = fma2(bw0, k0p[p], acc);
            acc = fma2(bw1, k1p[p], acc);
            acc = fma2(bw2, k2p[p], acc);
            acc = fma2(bw3, k3p[p], acc);
            acc = fma2(bw4, k4p[p], acc);
            zp[p] = acc;
        }
    } // steps

    // readout: per-warp partial dots, reduce via smem
    {
        float partA = 0.0f, partB = 0.0f;
#pragma unroll
        for (int p = 0; p < 8; p++) {
            float zA, zB;
            unpack2(zp[p], zA, zB);
            float wr = wrog[8 * w + p];
            partA = fmaf(zA, wr, partA);
            partB = fmaf(zB, wr, partB);
        }
        float* red = (float*)ysm;  // 256 floats scratch
        red[w * 32 + lane]       = partA;
        red[128 + w * 32 + lane] = partB;
        __syncthreads();
        if (tid < 64) {
            int which = tid >> 5;         // 0 = A-half, 1 = B-half
            int l     = tid & 31;
            int base  = which * 128;
            float logit = red[base + l] + red[base + 32 + l] +
                          red[base + 64 + l] + red[base + 96 + l] + brog[0];
            out[g * 64 + which * 32 + l] = __fdividef(1.0f, 1.0f + __expf(-logit));
        }
    }
}

extern "C" void kernel_launch(void* const* d_in, const int* in_sizes, int n_in,
                              void* d_out, int out_size)
{
    const float* times = (const float*)d_in[0];
    const float* grads = (const float*)d_in[1];
    const float* w1    = (const float*)d_in[2];
    const float* b1    = (const float*)d_in[3];
    const float* w2    = (const float*)d_in[4];
    const float* b2    = (const float*)d_in[5];
    const float* w3    = (const float*)d_in[6];
    const float* b3    = (const float*)d_in[7];
    const float* wenc  = (const float*)d_in[8];
    const float* benc  = (const float*)d_in[9];
    const float* wro   = (const float*)d_in[10];
    const float* bro   = (const float*)d_in[11];
    float* out = (float*)d_out;

    cudaFuncSetAttribute(neural_cde_kernel,
                         cudaFuncAttributeMaxDynamicSharedMemorySize, SMEM_BYTES);

    neural_cde_kernel<<<GRID, BLK, SMEM_BYTES>>>(
        times, grads, w1, b1, w2, b2, w3, b3, wenc, benc, wro, bro, out);
}

// round 7
// speedup vs baseline: 1.0010x; 1.0010x over previous
#include <cuda_runtime.h>
#include <math.h>

#define B_TOTAL 16384
#define T_LEN   512
#define NSTEP   511
#define HDIM    32
#define WID     64
#define BLK     128
#define NGROUPS 256          /* 16384 / 64 elements per CTA */
#define GRID    256

typedef unsigned long long u64;

// Tsit5 coefficients
__constant__ float cA[6][5] = {
    {0.f, 0.f, 0.f, 0.f, 0.f},
    {0.161f, 0.f, 0.f, 0.f, 0.f},
    {-0.008480655492356989f, 0.335480655492357f, 0.f, 0.f, 0.f},
    {2.8971530571054935f, -6.359448489975075f, 4.3622954328695815f, 0.f, 0.f},
    {5.325864828439257f, -11.748883564062828f, 7.4955393428898365f, -0.09249506636175525f, 0.f},
    {5.86145544294642f, -12.92096931784711f, 8.159367898576159f, -0.071584973281401f, -0.028269050394068383f}
};
__constant__ float cB[6] = {
    0.09646076681806523f, 0.01f, 0.4798896504144996f,
    1.379008574103742f, -3.290069515436081f, 2.324710524099774f
};

// ---- packed f32x2 helpers ----
__device__ __forceinline__ u64 pack2(float lo, float hi) {
    u64 r; asm("mov.b64 %0, {%1, %2};" : "=l"(r) : "f"(lo), "f"(hi)); return r;
}
__device__ __forceinline__ void unpack2(u64 v, float& lo, float& hi) {
    asm("mov.b64 {%0, %1}, %2;" : "=f"(lo), "=f"(hi) : "l"(v));
}
__device__ __forceinline__ u64 dup2(float x) { return pack2(x, x); }
__device__ __forceinline__ u64 fma2(u64 a, u64 b, u64 c) {
    u64 d; asm("fma.rn.f32x2 %0, %1, %2, %3;" : "=l"(d) : "l"(a), "l"(b), "l"(c)); return d;
}

// SMEM layout (floats)
#define OFF_W1T 0                      /* [i=32][j=64] transposed : 2048 */
#define OFF_W2T (OFF_W1T + 2048)       /* [i=64][j=64]            : 4096 */
#define OFF_W3T (OFF_W2T + 4096)       /* [i=64][r=96]            : 6144 */
#define OFF_B1  (OFF_W3T + 6144)       /* 64 */
#define OFF_B2  (OFF_B1 + 64)          /* 64 */
#define OFF_B3  (OFF_B2 + 64)          /* 96 */
#define OFF_Y   (OFF_B3 + 96)          /* u64 [32 comp][32 lane] : 2048 floats */
#define OFF_H1  (OFF_Y + 2048)         /* u64 [64][32] : 4096 floats */
#define OFF_H2  (OFF_H1 + 4096)        /* u64 [64][32] : 4096 floats */
#define SMEM_FLOATS (OFF_H2 + 4096)
#define SMEM_BYTES  (SMEM_FLOATS * 4)  /* 91,008 B -> 2 CTAs/SM */

__device__ __forceinline__ float tanh_fast(float x) {
    float xc = fminf(fmaxf(x, -15.0f), 15.0f);
    float e  = __expf(2.0f * xc);
    return __fdividef(e - 1.0f, e + 1.0f);
}

__global__ void __launch_bounds__(BLK, 2)
neural_cde_kernel(const float* __restrict__ times,
                  const float* __restrict__ grads,
                  const float* __restrict__ w1g,
                  const float* __restrict__ b1g,
                  const float* __restrict__ w2g,
                  const float* __restrict__ b2g,
                  const float* __restrict__ w3g,
                  const float* __restrict__ b3g,
                  const float* __restrict__ wencg,
                  const float* __restrict__ bencg,
                  const float* __restrict__ wrog,
                  const float* __restrict__ brog,
                  float* __restrict__ out)
{
    extern __shared__ float sm[];
    float* w1t  = sm + OFF_W1T;
    float* w2t  = sm + OFF_W2T;
    float* w3t  = sm + OFF_W3T;
    float* b1s  = sm + OFF_B1;
    float* b2s  = sm + OFF_B2;
    float* b3s  = sm + OFF_B3;
    u64*   ysm  = (u64*)(sm + OFF_Y);
    u64*   h1sm = (u64*)(sm + OFF_H1);
    u64*   h2sm = (u64*)(sm + OFF_H2);

    const int tid  = threadIdx.x;
    const int w    = tid >> 5;
    const int lane = tid & 31;

    // ---- stage weights (transposed) ----
    for (int idx = tid; idx < 2048; idx += BLK) {        // w1: [64][32] -> w1t[i][j]
        int j = idx >> 5, i = idx & 31;
        w1t[i * 64 + j] = w1g[idx];
    }
    for (int idx = tid; idx < 4096; idx += BLK) {        // w2: [64][64] -> w2t[i][j]
        int j = idx >> 6, i = idx & 63;
        w2t[i * 64 + j] = w2g[idx];
    }
    for (int idx = tid; idx < 6144; idx += BLK) {        // w3: [96][64] -> w3t[i][r]
        int r = idx >> 6, i = idx & 63;
        w3t[i * 96 + r] = w3g[idx];
    }
    for (int idx = tid; idx < 64; idx += BLK) b1s[idx] = b1g[idx];
    for (int idx = tid; idx < 64; idx += BLK) b2s[idx] = b2g[idx];
    for (int idx = tid; idx < 96; idx += BLK) b3s[idx] = b3g[idx];
    __syncthreads();

    const float dt = times[1] - times[0];

    const int g  = blockIdx.x;
    const int eA = g * 64 + lane;
    const int eB = eA + 32;
    const float* gA = grads + (size_t)eA * T_LEN * 3;
    const float* gB = grads + (size_t)eB * T_LEN * 3;

    // packed per-thread state: comps [8w,8w+8), halves = (elemA, elemB)
    u64 zp[8], k0p[8], k1p[8], k2p[8], k3p[8], k4p[8], kvp[8];
#pragma unroll
    for (int p = 0; p < 8; p++) {
        int c = 8 * w + p;
        zp[p] = dup2(wencg[c] + bencg[c]);
        k0p[p] = k1p[p] = k2p[p] = k3p[p] = k4p[p] = 0ull;
    }

    const u64 bw0 = dup2(cB[0]), bw1 = dup2(cB[1]), bw2 = dup2(cB[2]);
    const u64 bw3 = dup2(cB[3]), bw4 = dup2(cB[4]), bw5 = dup2(cB[5]);

#pragma unroll 1
    for (int n = 0; n < NSTEP; n++) {
        const float dqA0 = gA[n * 3 + 0] * dt;
        const float dqA1 = gA[n * 3 + 1] * dt;
        const float dqA2 = gA[n * 3 + 2] * dt;
        const float dqB0 = gB[n * 3 + 0] * dt;
        const float dqB1 = gB[n * 3 + 1] * dt;
        const float dqB2 = gB[n * 3 + 2] * dt;

#pragma unroll 1
        for (int s = 0; s < 6; s++) {
            const u64 a0 = dup2(cA[s][0]), a1 = dup2(cA[s][1]);
            const u64 a2 = dup2(cA[s][2]), a3 = dup2(cA[s][3]);
            const u64 a4 = dup2(cA[s][4]);

            // phase 1: y slice -> smem (zero coeffs are exact no-ops)
#pragma unroll
            for (int p = 0; p < 8; p++) {
                u64 acc = zp[p];
                acc = fma2(a0, k0p[p], acc);
                acc = fma2(a1, k1p[p], acc);
                acc = fma2(a2, k2p[p], acc);
                acc = fma2(a3, k3p[p], acc);
                acc = fma2(a4, k4p[p], acc);
                ysm[(8 * w + p) * 32 + lane] = acc;
            }
            __syncthreads();

            // phase 2: L1 rows [16w,16w+16); acc pairs over (r, r+1)
            {
                u64 accA[8], accB[8];
                const u64* bp = (const u64*)(b1s + 16 * w);
#pragma unroll
                for (int u = 0; u < 8; u++) { accA[u] = bp[u]; accB[u] = bp[u]; }
#pragma unroll 8
                for (int i = 0; i < HDIM; i++) {
                    float yA, yB;
                    unpack2(ysm[i * 32 + lane], yA, yB);
                    const u64 dA = dup2(yA), dB = dup2(yB);
                    const ulonglong2* wp = (const ulonglong2*)(w1t + i * 64 + 16 * w);
#pragma unroll
                    for (int q = 0; q < 4; q++) {
                        ulonglong2 wq = wp[q];
                        accA[2 * q + 0] = fma2(wq.x, dA, accA[2 * q + 0]);
                        accA[2 * q + 1] = fma2(wq.y, dA, accA[2 * q + 1]);
                        accB[2 * q + 0] = fma2(wq.x, dB, accB[2 * q + 0]);
                        accB[2 * q + 1] = fma2(wq.y, dB, accB[2 * q + 1]);
                    }
                }
#pragma unroll
                for (int u = 0; u < 8; u++) {
                    float aA0, aA1, aB0, aB1;
                    unpack2(accA[u], aA0, aA1);
                    unpack2(accB[u], aB0, aB1);
                    int r0 = 16 * w + 2 * u;
                    h1sm[r0 * 32 + lane]       = pack2(tanh_fast(aA0), tanh_fast(aB0));
                    h1sm[(r0 + 1) * 32 + lane] = pack2(tanh_fast(aA1), tanh_fast(aB1));
                }
            }
            __syncthreads();

            // phase 3: L2 rows [16w,16w+16)
            {
                u64 accA[8], accB[8];
                const u64* bp = (const u64*)(b2s + 16 * w);
#pragma unroll
                for (int u = 0; u < 8; u++) { accA[u] = bp[u]; accB[u] = bp[u]; }
#pragma unroll 8
                for (int i = 0; i < WID; i++) {
                    float hA, hB;
                    unpack2(h1sm[i * 32 + lane], hA, hB);
                    const u64 dA = dup2(hA), dB = dup2(hB);
                    const ulonglong2* wp = (const ulonglong2*)(w2t + i * 64 + 16 * w);
#pragma unroll
                    for (int q = 0; q < 4; q++) {
                        ulonglong2 wq = wp[q];
                        accA[2 * q + 0] = fma2(wq.x, dA, accA[2 * q + 0]);
                        accA[2 * q + 1] = fma2(wq.y, dA, accA[2 * q + 1]);
                        accB[2 * q + 0] = fma2(wq.x, dB, accB[2 * q + 0]);
                        accB[2 * q + 1] = fma2(wq.y, dB, accB[2 * q + 1]);
                    }
                }
#pragma unroll
                for (int u = 0; u < 8; u++) {
                    float aA0, aA1, aB0, aB1;
                    unpack2(accA[u], aA0, aA1);
                    unpack2(accB[u], aB0, aB1);
                    int r0 = 16 * w + 2 * u;
                    h2sm[r0 * 32 + lane]       = pack2(tanh_fast(aA0), tanh_fast(aB0));
                    h2sm[(r0 + 1) * 32 + lane] = pack2(tanh_fast(aA1), tanh_fast(aB1));
                }
            }
            __syncthreads();

            // phase 4: L3 rows [24w,24w+24) + dq contraction
            {
                u64 accA[12], accB[12];
                const u64* bp = (const u64*)(b3s + 24 * w);
#pragma unroll
                for (int u = 0; u < 12; u++) { accA[u] = bp[u]; accB[u] = bp[u]; }
#pragma unroll 8
                for (int i = 0; i < WID; i++) {
                    float hA, hB;
                    unpack2(h2sm[i * 32 + lane], hA, hB);
                    const u64 dA = dup2(hA), dB = dup2(hB);
                    const ulonglong2* wp = (const ulonglong2*)(w3t + i * 96 + 24 * w);
#pragma unroll
                    for (int q = 0; q < 6; q++) {
                        ulonglong2 wq = wp[q];
                        accA[2 * q + 0] = fma2(wq.x, dA, accA[2 * q + 0]);
                        accA[2 * q + 1] = fma2(wq.y, dA, accA[2 * q + 1]);
                        accB[2 * q + 0] = fma2(wq.x, dB, accB[2 * q + 0]);
                        accB[2 * q + 1] = fma2(wq.y, dB, accB[2 * q + 1]);
                    }
                }
                float fA[24], fB[24];
#pragma unroll
                for (int u = 0; u < 12; u++) {
                    unpack2(accA[u], fA[2 * u], fA[2 * u + 1]);
                    unpack2(accB[u], fB[2 * u], fB[2 * u + 1]);
                }
#pragma unroll
                for (int p = 0; p < 8; p++) {
                    float kA = fA[3 * p] * dqA0;
                    kA = fmaf(fA[3 * p + 1], dqA1, kA);
                    kA = fmaf(fA[3 * p + 2], dqA2, kA);
                    float kB = fB[3 * p] * dqB0;
                    kB = fmaf(fB[3 * p + 1], dqB1, kB);
                    kB = fmaf(fB[3 * p + 2], dqB2, kB);
                    kvp[p] = pack2(kA, kB);
                }
            }

            if (s == 0) {
#pragma unroll
                for (int p = 0; p < 8; p++) k0p[p] = kvp[p];
            } else if (s == 1) {
#pragma unroll
                for (int p = 0; p < 8; p++) k1p[p] = kvp[p];
            } else if (s == 2) {
#pragma unroll
                for (int p = 0; p < 8; p++) k2p[p] = kvp[p];
            } else if (s == 3) {
#pragma unroll
                for (int p = 0; p < 8; p++) k3p[p] = kvp[p];
            } else if (s == 4) {
#pragma unroll
                for (int p = 0; p < 8; p++) k4p[p] = kvp[p];
            }
        } // stages

#pragma unroll
        for (int p = 0; p < 8; p++) {
            u64 acc = fma2(bw5, kvp[p], zp[p]);
            acc = fma2(bw0, k0p[p], acc);
            acc = fma2(bw1, k1p[p], acc);
            acc = fma2(bw2, k2p[p], acc);
            acc = fma2(bw3, k3p[p], acc);
            acc = fma2(bw4, k4p[p], acc);
            zp[p] = acc;
        }
    } // steps

    // readout: per-warp partial dots, reduce via smem
    {
        float partA = 0.0f, partB = 0.0f;
#pragma unroll
        for (int p = 0; p < 8; p++) {
            float zA, zB;
            unpack2(zp[p], zA, zB);
            float wr = wrog[8 * w + p];
            partA = fmaf(zA, wr, partA);
            partB = fmaf(zB, wr, partB);
        }
        float* red = (float*)ysm;  // 256 floats scratch
        red[w * 32 + lane]       = partA;
        red[128 + w * 32 + lane] = partB;
        __syncthreads();
        if (tid < 64) {
            int which = tid >> 5;         // 0 = A-half, 1 = B-half
            int l     = tid & 31;
            int base  = which * 128;
            float logit = red[base + l] + red[base + 32 + l] +
                          red[base + 64 + l] + red[base + 96 + l] + brog[0];
            out[g * 64 + which * 32 + l] = __fdividef(1.0f, 1.0f + __expf(-logit));
        }
    }
}

extern "C" void kernel_launch(void* const* d_in, const int* in_sizes, int n_in,
                              void* d_out, int out_size)
{
    const float* times = (const float*)d_in[0];
    const float* grads = (const float*)d_in[1];
    const float* w1    = (const float*)d_in[2];
    const float* b1    = (const float*)d_in[3];
    const float* w2    = (const float*)d_in[4];
    const float* b2    = (const float*)d_in[5];
    const float* w3    = (const float*)d_in[6];
    const float* b3    = (const float*)d_in[7];
    const float* wenc  = (const float*)d_in[8];
    const float* benc  = (const float*)d_in[9];
    const float* wro   = (const float*)d_in[10];
    const float* bro   = (const float*)d_in[11];
    float* out = (float*)d_out;

    cudaFuncSetAttribute(neural_cde_kernel,
                         cudaFuncAttributeMaxDynamicSharedMemorySize, SMEM_BYTES);

    neural_cde_kernel<<<GRID, BLK, SMEM_BYTES>>>(
        times, grads, w1, b1, w2, b2, w3, b3, wenc, benc, wro, bro, out);
}